// round 8
// baseline (speedup 1.0000x reference)
#include <cuda_runtime.h>
#include <cuda_bf16.h>
#include <cstdint>

// ===========================================================================
// MoE AG-scatter grouped GEMM via mma.sync bf16, 2-term fp32 split (3 products)
//   out[s,:] = x[token(s),:] @ W[e(s),:,:]^T
// R8: R7 (BK=32, 3-stage cp.async, 1 barrier/chunk, XOR-swizzled 64B rows,
//     CTA 128x128, 8 warps 4Mx2N, 2 CTAs/SM, persistent) + CROSS-JOB
//     PIPELINING: next job's first two stages are issued before the current
//     job's epilogue, hiding prologue refill + epilogue behind each other.
// ===========================================================================

#define NTOK   8192
#define TOPK   2
#define MTOT   (NTOK * TOPK)          // 16384
#define NDIM   1024
#define KDIM   1024
#define NEXP   8

#define BM     128
#define BN     128
#define BK     32                     // bf16 k per chunk
#define NCHUNK (KDIM / BK)            // 32
#define NSTAGE 3
#define NBLK   (NDIM / BN)            // 8
#define MAXTILES (MTOT / BM + NEXP)   // 136

#define RSTR   64                     // unpadded row stride (bytes)
#define OFF_AH 0
#define OFF_AL (128 * RSTR)
#define OFF_BH (2 * 128 * RSTR)
#define OFF_BL (3 * 128 * RSTR)
#define STAGE_BYTES (4 * 128 * RSTR)  // 32768
#define SMEM_TOTAL  (NSTAGE * STAGE_BYTES + 1024 + 16)

// ---------------- device-global scratch ------------------------------------
__device__ int g_token_of_row[MTOT];
__device__ int g_tile_e[MAXTILES];
__device__ int g_tile_row0[MAXTILES];
__device__ int g_tile_rows[MAXTILES];
__device__ int g_njobs;
__device__ int g_job;
__device__ __align__(16) __nv_bfloat16 g_A_hi[(size_t)NTOK * KDIM];
__device__ __align__(16) __nv_bfloat16 g_A_lo[(size_t)NTOK * KDIM];
__device__ __align__(16) __nv_bfloat16 g_W_hi[(size_t)NEXP * NDIM * KDIM];
__device__ __align__(16) __nv_bfloat16 g_W_lo[(size_t)NEXP * NDIM * KDIM];

// ---------------- helpers ---------------------------------------------------
__device__ __forceinline__ uint32_t smem_to_u32(const void* p) {
    uint32_t a;
    asm("{ .reg .u64 t; cvta.to.shared.u64 t, %1; cvt.u32.u64 %0, t; }"
        : "=r"(a) : "l"(p));
    return a;
}

#define CPA16(dst_u32, src_ptr) \
    asm volatile("cp.async.cg.shared.global [%0], [%1], 16;" \
        :: "r"(dst_u32), "l"(src_ptr))
#define CPA_COMMIT() asm volatile("cp.async.commit_group;")
#define CPA_WAIT1()  asm volatile("cp.async.wait_group 1;")
#define CPA_WAIT0()  asm volatile("cp.async.wait_group 0;")

__device__ __forceinline__ void ldsm_x4(uint32_t r[4], uint32_t addr) {
    asm volatile("ldmatrix.sync.aligned.m8n8.x4.shared.b16 {%0,%1,%2,%3}, [%4];"
        : "=r"(r[0]), "=r"(r[1]), "=r"(r[2]), "=r"(r[3]) : "r"(addr));
}

__device__ __forceinline__ void mma_bf16(float d[4],
    const uint32_t a[4], uint32_t b0, uint32_t b1)
{
    asm volatile(
        "mma.sync.aligned.m16n8k16.row.col.f32.bf16.bf16.f32 "
        "{%0,%1,%2,%3}, {%4,%5,%6,%7}, {%8,%9}, {%0,%1,%2,%3};"
        : "+f"(d[0]), "+f"(d[1]), "+f"(d[2]), "+f"(d[3])
        : "r"(a[0]), "r"(a[1]), "r"(a[2]), "r"(a[3]), "r"(b0), "r"(b1));
}

__device__ __forceinline__ void split_store(float4 v, __nv_bfloat16* hi,
                                            __nv_bfloat16* lo, size_t o)
{
    __nv_bfloat16 h0 = __float2bfloat16(v.x), h1 = __float2bfloat16(v.y);
    __nv_bfloat16 h2 = __float2bfloat16(v.z), h3 = __float2bfloat16(v.w);
    __nv_bfloat16 l0 = __float2bfloat16(v.x - __bfloat162float(h0));
    __nv_bfloat16 l1 = __float2bfloat16(v.y - __bfloat162float(h1));
    __nv_bfloat16 l2 = __float2bfloat16(v.z - __bfloat162float(h2));
    __nv_bfloat16 l3 = __float2bfloat16(v.w - __bfloat162float(h3));
    *(ushort4*)(hi + o) = make_ushort4(
        __bfloat16_as_ushort(h0), __bfloat16_as_ushort(h1),
        __bfloat16_as_ushort(h2), __bfloat16_as_ushort(h3));
    *(ushort4*)(lo + o) = make_ushort4(
        __bfloat16_as_ushort(l0), __bfloat16_as_ushort(l1),
        __bfloat16_as_ushort(l2), __bfloat16_as_ushort(l3));
}

// ---------------- fused prep -------------------------------------------------
#define WBLK 8192
#define ABLK 8192
#define MBLK (MTOT / 256)             // 64
#define PREP_GRID (WBLK + ABLK + MBLK + 1)

__global__ __launch_bounds__(256) void prep_all(
    const float* __restrict__ x, const float* __restrict__ w,
    const int* __restrict__ scatter, const int* __restrict__ splits)
{
    int b = blockIdx.x;
    if (b < WBLK) {
        size_t o = ((size_t)b * 256 + threadIdx.x) * 4;
        split_store(*(const float4*)(w + o), g_W_hi, g_W_lo, o);
    } else if (b < WBLK + ABLK) {
        size_t o = ((size_t)(b - WBLK) * 256 + threadIdx.x) * 4;
        split_store(*(const float4*)(x + o), g_A_hi, g_A_lo, o);
    } else if (b < WBLK + ABLK + MBLK) {
        int f = (b - WBLK - ABLK) * 256 + threadIdx.x;
        g_token_of_row[scatter[f]] = f / TOPK;
    } else if (threadIdx.x == 0) {
        int cum = 0, t = 0;
        for (int e = 0; e < NEXP; e++) {
            int cnt = splits[e];
            for (int r0 = 0; r0 < cnt; r0 += BM) {
                g_tile_e[t] = e;
                g_tile_row0[t] = cum + r0;
                g_tile_rows[t] = (cnt - r0 < BM) ? (cnt - r0) : BM;
                t++;
            }
            cum += cnt;
        }
        g_njobs = t * NBLK;
        g_job = 0;
    }
}

// ---------------- main GEMM --------------------------------------------------
__device__ __forceinline__ void load_stage(uint32_t sbuf, int c, int wbase,
                                           const int* s_tok, int tid)
{
    const size_t kb = (size_t)c * BK;
    #pragma unroll
    for (int i = 0; i < 8; i++) {
        int o   = tid + i * 256;          // 0..2047
        int t4  = o >> 9;                 // 0=Ah,1=Al,2=Bh,3=Bl
        int r   = (o >> 2) & 127;
        int seg = o & 3;
        int sw  = seg ^ ((r >> 1) & 3);   // XOR swizzle
        uint32_t dst = sbuf + t4 * (128 * RSTR) + r * RSTR + sw * 16;
        const char* src;
        if (t4 < 2) {
            int tok = s_tok[r];
            const __nv_bfloat16* base = (t4 == 0) ? g_A_hi : g_A_lo;
            src = (const char*)(base + (size_t)tok * KDIM + kb) + seg * 16;
        } else {
            const __nv_bfloat16* base = (t4 == 2) ? g_W_hi : g_W_lo;
            src = (const char*)(base + (size_t)(wbase + r) * KDIM + kb) + seg * 16;
        }
        CPA16(dst, src);
    }
}

__global__ __launch_bounds__(256, 2) void moe_gemm_mma(float* __restrict__ out)
{
    extern __shared__ char smem_raw[];
    const uint32_t stage0 = smem_to_u32(smem_raw);
    int* s_tok0 = (int*)(smem_raw + NSTAGE * STAGE_BYTES);
    int* s_tok1 = s_tok0 + 128;
    int* s_job  = s_tok0 + 256;

    const int tid  = threadIdx.x;
    const int wid  = tid >> 5;
    const int lane = tid & 31;
    const int wm   = wid & 3;          // 4 warps along M (32 rows each)
    const int wn   = wid >> 2;         // 2 warps along N (64 cols each)

    // ldmatrix lane rows + per-row swizzle masks
    const int a_r   = (lane & 7) + ((lane >> 3) & 1) * 8;
    const int a_c16 = lane >> 4;
    uint32_t rowA[2]; int mA[2];
    #pragma unroll
    for (int mt = 0; mt < 2; mt++) {
        int r = wm * 32 + mt * 16 + a_r;
        rowA[mt] = r * RSTR;
        mA[mt] = (r >> 1) & 3;
    }
    const int b_r   = (lane & 7) + ((lane >> 4) & 1) * 8;
    const int b_k16 = (lane >> 3) & 1;
    uint32_t rowB[4]; int mB[4];
    #pragma unroll
    for (int np = 0; np < 4; np++) {
        int r = wn * 64 + np * 16 + b_r;
        rowB[np] = r * RSTR;
        mB[np] = (r >> 1) & 3;
    }

    const int njobs = g_njobs;

    // ---- initial job fetch + first prologue ----
    if (tid == 0) *s_job = atomicAdd(&g_job, 1);
    __syncthreads();
    int job = *s_job;
    int tbuf = 0;

    if (job < njobs) {
        const int tile = job >> 3;
        const int row0 = g_tile_row0[tile];
        const int nrows = g_tile_rows[tile];
        const int wbase = g_tile_e[tile] * NDIM + (job & 7) * BN;
        if (tid < 128)
            s_tok0[tid] = (tid < nrows) ? g_token_of_row[row0 + tid] : 0;
        __syncthreads();
        load_stage(stage0, 0, wbase, s_tok0, tid);
        CPA_COMMIT();
        load_stage(stage0 + STAGE_BYTES, 1, wbase, s_tok0, tid);
        CPA_COMMIT();
    }

    while (job < njobs) {
        const int tile  = job >> 3;
        const int nb    = job & 7;
        const int nrows = g_tile_rows[tile];
        const int row0  = g_tile_row0[tile];
        const int n0    = nb * BN;
        const int wbase = g_tile_e[tile] * NDIM + n0;
        const int* tokp = tbuf ? s_tok1 : s_tok0;

        float acc[2][8][4];
        #pragma unroll
        for (int mt = 0; mt < 2; mt++)
            #pragma unroll
            for (int nt = 0; nt < 8; nt++)
                #pragma unroll
                for (int q = 0; q < 4; q++)
                    acc[mt][nt][q] = 0.0f;

        uint32_t sbuf = stage0;
        for (int c = 0; c < NCHUNK; c++) {
            if (c < NCHUNK - 1) { CPA_WAIT1(); } else { CPA_WAIT0(); }
            __syncthreads();                      // single barrier per chunk

            if (c == NCHUNK - 4 && tid == 0)      // prefetch next job index
                *s_job = atomicAdd(&g_job, 1);

            if (c + 2 < NCHUNK) {
                uint32_t nbuf = sbuf + 2 * STAGE_BYTES;
                if (nbuf >= stage0 + 3 * STAGE_BYTES) nbuf -= 3 * STAGE_BYTES;
                load_stage(nbuf, c + 2, wbase, tokp, tid);
                CPA_COMMIT();
            }

            #pragma unroll
            for (int ks = 0; ks < 2; ks++) {
                uint32_t Ah[2][4], Al[2][4];
                #pragma unroll
                for (int mt = 0; mt < 2; mt++) {
                    const uint32_t ao = rowA[mt] +
                        (uint32_t)(((a_c16 + ks * 2) ^ mA[mt]) << 4);
                    ldsm_x4(Ah[mt], sbuf + OFF_AH + ao);
                    ldsm_x4(Al[mt], sbuf + OFF_AL + ao);
                }
                #pragma unroll
                for (int np = 0; np < 4; np++) {
                    const uint32_t bo = rowB[np] +
                        (uint32_t)(((b_k16 + ks * 2) ^ mB[np]) << 4);
                    uint32_t Bh[4], Bl[4];
                    ldsm_x4(Bh, sbuf + OFF_BH + bo);
                    ldsm_x4(Bl, sbuf + OFF_BL + bo);
                    #pragma unroll
                    for (int mt = 0; mt < 2; mt++) {
                        float* d0 = acc[mt][2 * np];
                        float* d1 = acc[mt][2 * np + 1];
                        mma_bf16(d0, Ah[mt], Bh[0], Bh[1]);
                        mma_bf16(d1, Ah[mt], Bh[2], Bh[3]);
                        mma_bf16(d0, Ah[mt], Bl[0], Bl[1]);
                        mma_bf16(d1, Ah[mt], Bl[2], Bl[3]);
                        mma_bf16(d0, Al[mt], Bh[0], Bh[1]);
                        mma_bf16(d1, Al[mt], Bh[2], Bh[3]);
                    }
                }
            }

            sbuf += STAGE_BYTES;
            if (sbuf >= stage0 + 3 * STAGE_BYTES) sbuf = stage0;
        }

        __syncthreads();                 // all warps done reading stage buffers

        // ---- issue next job's prologue BEFORE epilogue ----
        const int njob = *s_job;         // written at c==NCHUNK-4, ordered by barriers
        if (njob < njobs) {
            const int ntile = njob >> 3;
            const int nrow0 = g_tile_row0[ntile];
            const int nnr   = g_tile_rows[ntile];
            const int nwb   = g_tile_e[ntile] * NDIM + (njob & 7) * BN;
            int* ntok = tbuf ? s_tok0 : s_tok1;
            if (tid < 128)
                ntok[tid] = (tid < nnr) ? g_token_of_row[nrow0 + tid] : 0;
            __syncthreads();
            load_stage(stage0, 0, nwb, ntok, tid);
            CPA_COMMIT();
            load_stage(stage0 + STAGE_BYTES, 1, nwb, ntok, tid);
            CPA_COMMIT();
        }

        // ---- epilogue (overlaps the in-flight cp.async) ----
        const int g = lane >> 2;
        const int t = lane & 3;
        #pragma unroll
        for (int mt = 0; mt < 2; mt++) {
            const int mBase = wm * 32 + mt * 16;
            const int m0 = mBase + g;
            const int m1 = mBase + g + 8;
            float* r0p = out + (size_t)(row0 + m0) * NDIM + n0 + wn * 64 + 2 * t;
            float* r1p = out + (size_t)(row0 + m1) * NDIM + n0 + wn * 64 + 2 * t;
            #pragma unroll
            for (int nt = 0; nt < 8; nt++) {
                if (m0 < nrows) {
                    float2 v; v.x = acc[mt][nt][0]; v.y = acc[mt][nt][1];
                    *(float2*)(r0p + nt * 8) = v;
                }
                if (m1 < nrows) {
                    float2 v; v.x = acc[mt][nt][2]; v.y = acc[mt][nt][3];
                    *(float2*)(r1p + nt * 8) = v;
                }
            }
        }

        job = njob;
        tbuf ^= 1;
    }
}

// ---------------------------------------------------------------------------
extern "C" void kernel_launch(void* const* d_in, const int* in_sizes, int n_in,
                              void* d_out, int out_size) {
    const float* x       = (const float*)d_in[0];
    const float* weights = (const float*)d_in[1];
    const int*   scatter = (const int*)d_in[2];
    const int*   splits  = (const int*)d_in[3];
    float*       out     = (float*)d_out;
    (void)in_sizes; (void)n_in; (void)out_size;

    cudaFuncSetAttribute(moe_gemm_mma,
                         cudaFuncAttributeMaxDynamicSharedMemorySize, SMEM_TOTAL);

    prep_all<<<PREP_GRID, 256>>>(x, weights, scatter, splits);
    moe_gemm_mma<<<304, 256, SMEM_TOTAL>>>(out);   // persistent, 2 CTAs/SM
}

// round 9
// speedup vs baseline: 1.1892x; 1.1892x over previous
#include <cuda_runtime.h>
#include <cuda_bf16.h>
#include <cstdint>

// ===========================================================================
// MoE AG-scatter grouped GEMM via mma.sync bf16, 2-term fp32 split (3 products)
//   out[s,:] = x[token(s),:] @ W[e(s),:,:]^T
// R9 = R7 (proven 254us: BK=32, 3-stage cp.async, 1 barrier/chunk, XOR swizzle,
//      CTA 128x128, 8 warps 4Mx2N, 2 CTAs/SM, persistent jobs) with:
//   (a) load_stage moved mid-chunk (after ks=0 half) so post-barrier ldsm/MMA
//       restart is not delayed by the LDGSTS burst;
//   (b) prep with 2 independent float4/thread (MLP=2) for higher HBM util.
// ===========================================================================

#define NTOK   8192
#define TOPK   2
#define MTOT   (NTOK * TOPK)          // 16384
#define NDIM   1024
#define KDIM   1024
#define NEXP   8

#define BM     128
#define BN     128
#define BK     32                     // bf16 k per chunk
#define NCHUNK (KDIM / BK)            // 32
#define NSTAGE 3
#define NBLK   (NDIM / BN)            // 8
#define MAXTILES (MTOT / BM + NEXP)   // 136

#define RSTR   64                     // unpadded row stride (bytes)
#define OFF_AH 0
#define OFF_AL (128 * RSTR)
#define OFF_BH (2 * 128 * RSTR)
#define OFF_BL (3 * 128 * RSTR)
#define STAGE_BYTES (4 * 128 * RSTR)  // 32768
#define SMEM_TOTAL  (NSTAGE * STAGE_BYTES + 512 + 16)

// ---------------- device-global scratch ------------------------------------
__device__ int g_token_of_row[MTOT];
__device__ int g_tile_e[MAXTILES];
__device__ int g_tile_row0[MAXTILES];
__device__ int g_tile_rows[MAXTILES];
__device__ int g_njobs;
__device__ int g_job;
__device__ __align__(16) __nv_bfloat16 g_A_hi[(size_t)NTOK * KDIM];
__device__ __align__(16) __nv_bfloat16 g_A_lo[(size_t)NTOK * KDIM];
__device__ __align__(16) __nv_bfloat16 g_W_hi[(size_t)NEXP * NDIM * KDIM];
__device__ __align__(16) __nv_bfloat16 g_W_lo[(size_t)NEXP * NDIM * KDIM];

// ---------------- helpers ---------------------------------------------------
__device__ __forceinline__ uint32_t smem_to_u32(const void* p) {
    uint32_t a;
    asm("{ .reg .u64 t; cvta.to.shared.u64 t, %1; cvt.u32.u64 %0, t; }"
        : "=r"(a) : "l"(p));
    return a;
}

#define CPA16(dst_u32, src_ptr) \
    asm volatile("cp.async.cg.shared.global [%0], [%1], 16;" \
        :: "r"(dst_u32), "l"(src_ptr))
#define CPA_COMMIT() asm volatile("cp.async.commit_group;")
#define CPA_WAIT1()  asm volatile("cp.async.wait_group 1;")
#define CPA_WAIT0()  asm volatile("cp.async.wait_group 0;")

__device__ __forceinline__ void ldsm_x4(uint32_t r[4], uint32_t addr) {
    asm volatile("ldmatrix.sync.aligned.m8n8.x4.shared.b16 {%0,%1,%2,%3}, [%4];"
        : "=r"(r[0]), "=r"(r[1]), "=r"(r[2]), "=r"(r[3]) : "r"(addr));
}

__device__ __forceinline__ void mma_bf16(float d[4],
    const uint32_t a[4], uint32_t b0, uint32_t b1)
{
    asm volatile(
        "mma.sync.aligned.m16n8k16.row.col.f32.bf16.bf16.f32 "
        "{%0,%1,%2,%3}, {%4,%5,%6,%7}, {%8,%9}, {%0,%1,%2,%3};"
        : "+f"(d[0]), "+f"(d[1]), "+f"(d[2]), "+f"(d[3])
        : "r"(a[0]), "r"(a[1]), "r"(a[2]), "r"(a[3]), "r"(b0), "r"(b1));
}

__device__ __forceinline__ void split_store(float4 v, __nv_bfloat16* hi,
                                            __nv_bfloat16* lo, size_t o)
{
    __nv_bfloat16 h0 = __float2bfloat16(v.x), h1 = __float2bfloat16(v.y);
    __nv_bfloat16 h2 = __float2bfloat16(v.z), h3 = __float2bfloat16(v.w);
    __nv_bfloat16 l0 = __float2bfloat16(v.x - __bfloat162float(h0));
    __nv_bfloat16 l1 = __float2bfloat16(v.y - __bfloat162float(h1));
    __nv_bfloat16 l2 = __float2bfloat16(v.z - __bfloat162float(h2));
    __nv_bfloat16 l3 = __float2bfloat16(v.w - __bfloat162float(h3));
    *(ushort4*)(hi + o) = make_ushort4(
        __bfloat16_as_ushort(h0), __bfloat16_as_ushort(h1),
        __bfloat16_as_ushort(h2), __bfloat16_as_ushort(h3));
    *(ushort4*)(lo + o) = make_ushort4(
        __bfloat16_as_ushort(l0), __bfloat16_as_ushort(l1),
        __bfloat16_as_ushort(l2), __bfloat16_as_ushort(l3));
}

// ---------------- fused prep (2 float4 per thread, MLP=2) -------------------
#define WBLK 4096
#define ABLK 4096
#define MBLK (MTOT / 256)             // 64
#define PREP_GRID (WBLK + ABLK + MBLK + 1)

__global__ __launch_bounds__(256) void prep_all(
    const float* __restrict__ x, const float* __restrict__ w,
    const int* __restrict__ scatter, const int* __restrict__ splits)
{
    int b = blockIdx.x;
    if (b < WBLK + ABLK) {
        const bool isW = (b < WBLK);
        const float* src = isW ? w : x;
        __nv_bfloat16* hi = isW ? g_W_hi : g_A_hi;
        __nv_bfloat16* lo = isW ? g_W_lo : g_A_lo;
        size_t q = ((size_t)(isW ? b : b - WBLK) * 512 + threadIdx.x);
        size_t o0 = q * 4;
        size_t o1 = (q + 256) * 4;
        float4 v0 = *(const float4*)(src + o0);   // both loads in flight
        float4 v1 = *(const float4*)(src + o1);
        split_store(v0, hi, lo, o0);
        split_store(v1, hi, lo, o1);
    } else if (b < WBLK + ABLK + MBLK) {
        int f = (b - WBLK - ABLK) * 256 + threadIdx.x;
        g_token_of_row[scatter[f]] = f / TOPK;
    } else if (threadIdx.x == 0) {
        int cum = 0, t = 0;
        for (int e = 0; e < NEXP; e++) {
            int cnt = splits[e];
            for (int r0 = 0; r0 < cnt; r0 += BM) {
                g_tile_e[t] = e;
                g_tile_row0[t] = cum + r0;
                g_tile_rows[t] = (cnt - r0 < BM) ? (cnt - r0) : BM;
                t++;
            }
            cum += cnt;
        }
        g_njobs = t * NBLK;
        g_job = 0;
    }
}

// ---------------- main GEMM --------------------------------------------------
__device__ __forceinline__ void load_stage(uint32_t sbuf, int c, int wbase,
                                           const int* s_tok, int tid)
{
    const size_t kb = (size_t)c * BK;
    #pragma unroll
    for (int i = 0; i < 8; i++) {
        int o   = tid + i * 256;          // 0..2047
        int t4  = o >> 9;                 // 0=Ah,1=Al,2=Bh,3=Bl
        int r   = (o >> 2) & 127;
        int seg = o & 3;
        int sw  = seg ^ ((r >> 1) & 3);   // XOR swizzle
        uint32_t dst = sbuf + t4 * (128 * RSTR) + r * RSTR + sw * 16;
        const char* src;
        if (t4 < 2) {
            int tok = s_tok[r];
            const __nv_bfloat16* base = (t4 == 0) ? g_A_hi : g_A_lo;
            src = (const char*)(base + (size_t)tok * KDIM + kb) + seg * 16;
        } else {
            const __nv_bfloat16* base = (t4 == 2) ? g_W_hi : g_W_lo;
            src = (const char*)(base + (size_t)(wbase + r) * KDIM + kb) + seg * 16;
        }
        CPA16(dst, src);
    }
}

__global__ __launch_bounds__(256, 2) void moe_gemm_mma(float* __restrict__ out)
{
    extern __shared__ char smem_raw[];
    const uint32_t stage0 = smem_to_u32(smem_raw);
    int* s_tok = (int*)(smem_raw + NSTAGE * STAGE_BYTES);
    int* s_job = (int*)(smem_raw + NSTAGE * STAGE_BYTES + 512);

    const int tid  = threadIdx.x;
    const int wid  = tid >> 5;
    const int lane = tid & 31;
    const int wm   = wid & 3;          // 4 warps along M (32 rows each)
    const int wn   = wid >> 2;         // 2 warps along N (64 cols each)

    // ldmatrix lane rows + per-row swizzle masks
    const int a_r   = (lane & 7) + ((lane >> 3) & 1) * 8;
    const int a_c16 = lane >> 4;
    uint32_t rowA[2]; int mA[2];
    #pragma unroll
    for (int mt = 0; mt < 2; mt++) {
        int r = wm * 32 + mt * 16 + a_r;
        rowA[mt] = r * RSTR;
        mA[mt] = (r >> 1) & 3;
    }
    const int b_r   = (lane & 7) + ((lane >> 4) & 1) * 8;
    const int b_k16 = (lane >> 3) & 1;
    uint32_t rowB[4]; int mB[4];
    #pragma unroll
    for (int np = 0; np < 4; np++) {
        int r = wn * 64 + np * 16 + b_r;
        rowB[np] = r * RSTR;
        mB[np] = (r >> 1) & 3;
    }

    const int njobs = g_njobs;

    while (true) {
        __syncthreads();                          // smem free from previous job
        if (tid == 0) *s_job = atomicAdd(&g_job, 1);
        __syncthreads();
        const int job = *s_job;
        if (job >= njobs) break;

        const int tile = job >> 3;                // NBLK = 8
        const int nb   = job & 7;
        const int nrows = g_tile_rows[tile];
        const int row0  = g_tile_row0[tile];
        const int e     = g_tile_e[tile];
        const int n0    = nb * BN;
        const int wbase = e * NDIM + n0;

        if (tid < 128)
            s_tok[tid] = (tid < nrows) ? g_token_of_row[row0 + tid] : 0;
        __syncthreads();

        float acc[2][8][4];
        #pragma unroll
        for (int mt = 0; mt < 2; mt++)
            #pragma unroll
            for (int nt = 0; nt < 8; nt++)
                #pragma unroll
                for (int q = 0; q < 4; q++)
                    acc[mt][nt][q] = 0.0f;

        // prologue: 2 stages in flight
        load_stage(stage0, 0, wbase, s_tok, tid);
        CPA_COMMIT();
        load_stage(stage0 + STAGE_BYTES, 1, wbase, s_tok, tid);
        CPA_COMMIT();

        uint32_t sbuf = stage0;
        for (int c = 0; c < NCHUNK; c++) {
            if (c < NCHUNK - 1) { CPA_WAIT1(); } else { CPA_WAIT0(); }
            __syncthreads();                      // single barrier per chunk

            // ---- ks = 0 half: ldsm/MMA restart immediately ----
            #pragma unroll
            for (int ks = 0; ks < 1; ks++) {
                uint32_t Ah[2][4], Al[2][4];
                #pragma unroll
                for (int mt = 0; mt < 2; mt++) {
                    const uint32_t ao = rowA[mt] +
                        (uint32_t)(((a_c16) ^ mA[mt]) << 4);
                    ldsm_x4(Ah[mt], sbuf + OFF_AH + ao);
                    ldsm_x4(Al[mt], sbuf + OFF_AL + ao);
                }
                #pragma unroll
                for (int np = 0; np < 4; np++) {
                    const uint32_t bo = rowB[np] +
                        (uint32_t)(((b_k16) ^ mB[np]) << 4);
                    uint32_t Bh[4], Bl[4];
                    ldsm_x4(Bh, sbuf + OFF_BH + bo);
                    ldsm_x4(Bl, sbuf + OFF_BL + bo);
                    #pragma unroll
                    for (int mt = 0; mt < 2; mt++) {
                        float* d0 = acc[mt][2 * np];
                        float* d1 = acc[mt][2 * np + 1];
                        mma_bf16(d0, Ah[mt], Bh[0], Bh[1]);
                        mma_bf16(d1, Ah[mt], Bh[2], Bh[3]);
                        mma_bf16(d0, Ah[mt], Bl[0], Bl[1]);
                        mma_bf16(d1, Ah[mt], Bl[2], Bl[3]);
                        mma_bf16(d0, Al[mt], Bh[0], Bh[1]);
                        mma_bf16(d1, Al[mt], Bh[2], Bh[3]);
                    }
                }
            }

            // ---- issue next stage's loads while ks=0 MMAs drain ----
            if (c + 2 < NCHUNK) {
                uint32_t nbuf = sbuf + 2 * STAGE_BYTES;
                if (nbuf >= stage0 + 3 * STAGE_BYTES) nbuf -= 3 * STAGE_BYTES;
                load_stage(nbuf, c + 2, wbase, s_tok, tid);
                CPA_COMMIT();
            }

            // ---- ks = 1 half ----
            {
                uint32_t Ah[2][4], Al[2][4];
                #pragma unroll
                for (int mt = 0; mt < 2; mt++) {
                    const uint32_t ao = rowA[mt] +
                        (uint32_t)(((a_c16 + 2) ^ mA[mt]) << 4);
                    ldsm_x4(Ah[mt], sbuf + OFF_AH + ao);
                    ldsm_x4(Al[mt], sbuf + OFF_AL + ao);
                }
                #pragma unroll
                for (int np = 0; np < 4; np++) {
                    const uint32_t bo = rowB[np] +
                        (uint32_t)(((b_k16 + 2) ^ mB[np]) << 4);
                    uint32_t Bh[4], Bl[4];
                    ldsm_x4(Bh, sbuf + OFF_BH + bo);
                    ldsm_x4(Bl, sbuf + OFF_BL + bo);
                    #pragma unroll
                    for (int mt = 0; mt < 2; mt++) {
                        float* d0 = acc[mt][2 * np];
                        float* d1 = acc[mt][2 * np + 1];
                        mma_bf16(d0, Ah[mt], Bh[0], Bh[1]);
                        mma_bf16(d1, Ah[mt], Bh[2], Bh[3]);
                        mma_bf16(d0, Ah[mt], Bl[0], Bl[1]);
                        mma_bf16(d1, Ah[mt], Bl[2], Bl[3]);
                        mma_bf16(d0, Al[mt], Bh[0], Bh[1]);
                        mma_bf16(d1, Al[mt], Bh[2], Bh[3]);
                    }
                }
            }

            sbuf += STAGE_BYTES;
            if (sbuf >= stage0 + 3 * STAGE_BYTES) sbuf = stage0;
        }

        // epilogue
        const int g = lane >> 2;
        const int t = lane & 3;
        #pragma unroll
        for (int mt = 0; mt < 2; mt++) {
            const int mBase = wm * 32 + mt * 16;
            const int m0 = mBase + g;
            const int m1 = mBase + g + 8;
            float* r0p = out + (size_t)(row0 + m0) * NDIM + n0 + wn * 64 + 2 * t;
            float* r1p = out + (size_t)(row0 + m1) * NDIM + n0 + wn * 64 + 2 * t;
            #pragma unroll
            for (int nt = 0; nt < 8; nt++) {
                if (m0 < nrows) {
                    float2 v; v.x = acc[mt][nt][0]; v.y = acc[mt][nt][1];
                    *(float2*)(r0p + nt * 8) = v;
                }
                if (m1 < nrows) {
                    float2 v; v.x = acc[mt][nt][2]; v.y = acc[mt][nt][3];
                    *(float2*)(r1p + nt * 8) = v;
                }
            }
        }
    }
}

// ---------------------------------------------------------------------------
extern "C" void kernel_launch(void* const* d_in, const int* in_sizes, int n_in,
                              void* d_out, int out_size) {
    const float* x       = (const float*)d_in[0];
    const float* weights = (const float*)d_in[1];
    const int*   scatter = (const int*)d_in[2];
    const int*   splits  = (const int*)d_in[3];
    float*       out     = (float*)d_out;
    (void)in_sizes; (void)n_in; (void)out_size;

    cudaFuncSetAttribute(moe_gemm_mma,
                         cudaFuncAttributeMaxDynamicSharedMemorySize, SMEM_TOTAL);

    prep_all<<<PREP_GRID, 256>>>(x, weights, scatter, splits);
    moe_gemm_mma<<<304, 256, SMEM_TOTAL>>>(out);   // persistent, 2 CTAs/SM
}